// round 2
// baseline (speedup 1.0000x reference)
#include <cuda_runtime.h>
#include <cuda_bf16.h>
#include <cstdint>

#define NA 50000
#define NB 50000
#define D  128

// Scratch (device globals — no allocation allowed in kernel_launch).
// d_out itself is used as the accumulator for sum_r1 (A region) and sum_r0 (B region).
// g_sum2 holds the r2 (A->A) per-etype sum, since means are per-etype.
__device__ float g_sum2[(size_t)NA * D];
__device__ int   g_cnt0[NB];
__device__ int   g_cnt1[NA];
__device__ int   g_cnt2[NA];

// ---------------------------------------------------------------------------
// Zero accumulators: d_out (both regions), g_sum2, counts.
// ---------------------------------------------------------------------------
__global__ void zero_kernel(float4* __restrict__ out4, int nOut4, int nSum24) {
    int i = blockIdx.x * blockDim.x + threadIdx.x;
    const float4 z = make_float4(0.f, 0.f, 0.f, 0.f);
    if (i < nOut4)  out4[i] = z;
    if (i < nSum24) reinterpret_cast<float4*>(g_sum2)[i] = z;
    if (i < NB)     g_cnt0[i] = 0;
    if (i < NA)   { g_cnt1[i] = 0; g_cnt2[i] = 0; }
}

// ---------------------------------------------------------------------------
// Per-etype in-degree counts (int atomics).
// ---------------------------------------------------------------------------
__global__ void count_kernel(const int* __restrict__ dst0,
                             const int* __restrict__ dst1,
                             const int* __restrict__ dst2, int E) {
    int i = blockIdx.x * blockDim.x + threadIdx.x;
    if (i < E) {
        atomicAdd(&g_cnt0[dst0[i]], 1);
    } else if (i < 2 * E) {
        atomicAdd(&g_cnt1[dst1[i - E]], 1);
    } else if (i < 3 * E) {
        atomicAdd(&g_cnt2[dst2[i - 2 * E]], 1);
    }
}

// ---------------------------------------------------------------------------
// Edge scatter: warp per edge, lane c handles float4 chunk c of the D=128 row.
// Gather is coalesced (32 lanes read one 512B row); reduction uses
// red.global.add.v4.f32 (sm_90+) to quarter the atomic op count.
// ---------------------------------------------------------------------------
__device__ __forceinline__ void red_add_v4(float* p, float4 v) {
    asm volatile("red.global.add.v4.f32 [%0], {%1, %2, %3, %4};"
                 :: "l"(p), "f"(v.x), "f"(v.y), "f"(v.z), "f"(v.w)
                 : "memory");
}

__global__ void scatter_kernel(const float* __restrict__ emb,
                               const int*   __restrict__ src,
                               const int*   __restrict__ dst,
                               float*       __restrict__ sum, int E) {
    int t = blockIdx.x * blockDim.x + threadIdx.x;
    if (t >= E * 32) return;
    int e = t >> 5;          // edge id (one warp per edge)
    int c = t & 31;          // float4 chunk within the row
    int s = src[e];          // broadcast within warp
    int d = dst[e];
    float4 v = reinterpret_cast<const float4*>(emb + (size_t)s * D)[c];
    red_add_v4(sum + (size_t)d * D + (size_t)c * 4, v);
}

// ---------------------------------------------------------------------------
// Fused epilogue: per-etype mean, sum over etypes, + self embed + bias, relu.
// Thread = one float4 chunk. A region first, then B.
// ---------------------------------------------------------------------------
__global__ void epilogue_kernel(const float* __restrict__ selfA,
                                const float* __restrict__ selfB,
                                const float* __restrict__ bias,
                                float*       __restrict__ out) {
    int i = blockIdx.x * blockDim.x + threadIdx.x;
    const int total = (NA + NB) * (D / 4);
    if (i >= total) return;
    int node = i >> 5;       // D/4 = 32 chunks per node
    int c    = i & 31;

    float4 b4 = reinterpret_cast<const float4*>(bias)[c];
    float4* out4 = reinterpret_cast<float4*>(out);

    if (node < NA) {
        float4 s1 = out4[i];
        float4 s2 = reinterpret_cast<const float4*>(g_sum2)[i];
        float4 sf = reinterpret_cast<const float4*>(selfA)[i];
        float inv1 = 1.0f / fmaxf((float)g_cnt1[node], 1.0f);
        float inv2 = 1.0f / fmaxf((float)g_cnt2[node], 1.0f);
        float4 r;
        r.x = fmaxf(fmaf(s1.x, inv1, fmaf(s2.x, inv2, sf.x + b4.x)), 0.f);
        r.y = fmaxf(fmaf(s1.y, inv1, fmaf(s2.y, inv2, sf.y + b4.y)), 0.f);
        r.z = fmaxf(fmaf(s1.z, inv1, fmaf(s2.z, inv2, sf.z + b4.z)), 0.f);
        r.w = fmaxf(fmaf(s1.w, inv1, fmaf(s2.w, inv2, sf.w + b4.w)), 0.f);
        out4[i] = r;
    } else {
        int nb = node - NA;
        int j  = i - NA * (D / 4);
        float4 s0 = out4[i];
        float4 sf = reinterpret_cast<const float4*>(selfB)[j];
        float inv0 = 1.0f / fmaxf((float)g_cnt0[nb], 1.0f);
        float4 r;
        r.x = fmaxf(fmaf(s0.x, inv0, sf.x + b4.x), 0.f);
        r.y = fmaxf(fmaf(s0.y, inv0, sf.y + b4.y), 0.f);
        r.z = fmaxf(fmaf(s0.z, inv0, sf.z + b4.z), 0.f);
        r.w = fmaxf(fmaf(s0.w, inv0, sf.w + b4.w), 0.f);
        out4[i] = r;
    }
}

// ---------------------------------------------------------------------------
// Launch
// ---------------------------------------------------------------------------
extern "C" void kernel_launch(void* const* d_in, const int* in_sizes, int n_in,
                              void* d_out, int out_size) {
    const float* emb0  = (const float*)d_in[0];   // srctype A, etype r0 (A->B)
    const float* emb1  = (const float*)d_in[1];   // srctype B, etype r1 (B->A)
    const float* emb2  = (const float*)d_in[2];   // srctype A, etype r2 (A->A)
    const float* selfA = (const float*)d_in[3];
    const float* selfB = (const float*)d_in[4];
    const float* bias  = (const float*)d_in[5];
    const int* src0 = (const int*)d_in[6];
    const int* dst0 = (const int*)d_in[7];
    const int* src1 = (const int*)d_in[8];
    const int* dst1 = (const int*)d_in[9];
    const int* src2 = (const int*)d_in[10];
    const int* dst2 = (const int*)d_in[11];
    const int E = in_sizes[6];

    float* out   = (float*)d_out;
    float* sumA1 = out;                       // r1 mean accumulator (dst ntype A)
    float* sumB0 = out + (size_t)NA * D;      // r0 mean accumulator (dst ntype B)

    float* sum2_ptr = nullptr;
    cudaGetSymbolAddress((void**)&sum2_ptr, g_sum2);

    const int nOut4  = (NA + NB) * (D / 4);
    const int nSum24 = NA * (D / 4);

    zero_kernel<<<(nOut4 + 255) / 256, 256>>>((float4*)out, nOut4, nSum24);
    count_kernel<<<(3 * E + 255) / 256, 256>>>(dst0, dst1, dst2, E);

    const int scatterBlocks = (E * 32 + 255) / 256;
    scatter_kernel<<<scatterBlocks, 256>>>(emb0, src0, dst0, sumB0, E);
    scatter_kernel<<<scatterBlocks, 256>>>(emb1, src1, dst1, sumA1, E);
    scatter_kernel<<<scatterBlocks, 256>>>(emb2, src2, dst2, sum2_ptr, E);

    const int epiTotal = (NA + NB) * (D / 4);
    epilogue_kernel<<<(epiTotal + 255) / 256, 256>>>(selfA, selfB, bias, out);
}

// round 3
// speedup vs baseline: 1.0032x; 1.0032x over previous
#include <cuda_runtime.h>
#include <cuda_bf16.h>
#include <cstdint>

#define NA 50000
#define NB 50000
#define D  128

// Scratch (device globals — no allocation allowed in kernel_launch).
// d_out itself is used as the accumulator for sum_r1 (A region) and sum_r0 (B region).
// g_sum2 holds the r2 (A->A) per-etype sum, since means are per-etype.
__device__ float g_sum2[(size_t)NA * D];
__device__ int   g_cnt0[NB];
__device__ int   g_cnt1[NA];
__device__ int   g_cnt2[NA];

// ---------------------------------------------------------------------------
// Zero accumulators: d_out (both regions), g_sum2, counts.
// ---------------------------------------------------------------------------
__global__ void zero_kernel(float4* __restrict__ out4, int nOut4, int nSum24) {
    int i = blockIdx.x * blockDim.x + threadIdx.x;
    const float4 z = make_float4(0.f, 0.f, 0.f, 0.f);
    if (i < nOut4)  out4[i] = z;
    if (i < nSum24) reinterpret_cast<float4*>(g_sum2)[i] = z;
    if (i < NB)     g_cnt0[i] = 0;
    if (i < NA)   { g_cnt1[i] = 0; g_cnt2[i] = 0; }
}

// ---------------------------------------------------------------------------
// Per-etype in-degree counts (int atomics).
// ---------------------------------------------------------------------------
__global__ void count_kernel(const int* __restrict__ dst0,
                             const int* __restrict__ dst1,
                             const int* __restrict__ dst2, int E) {
    int i = blockIdx.x * blockDim.x + threadIdx.x;
    if (i < E) {
        atomicAdd(&g_cnt0[dst0[i]], 1);
    } else if (i < 2 * E) {
        atomicAdd(&g_cnt1[dst1[i - E]], 1);
    } else if (i < 3 * E) {
        atomicAdd(&g_cnt2[dst2[i - 2 * E]], 1);
    }
}

// ---------------------------------------------------------------------------
// Edge scatter: warp per edge, lane c handles float4 chunk c of the D=128 row.
// Gather is coalesced (32 lanes read one 512B row); reduction uses
// red.global.add.v4.f32 (sm_90+) to quarter the atomic op count.
// ---------------------------------------------------------------------------
__device__ __forceinline__ void red_add_v4(float* p, float4 v) {
    asm volatile("red.global.add.v4.f32 [%0], {%1, %2, %3, %4};"
                 :: "l"(p), "f"(v.x), "f"(v.y), "f"(v.z), "f"(v.w)
                 : "memory");
}

__global__ void scatter_kernel(const float* __restrict__ emb,
                               const int*   __restrict__ src,
                               const int*   __restrict__ dst,
                               float*       __restrict__ sum, int E) {
    int t = blockIdx.x * blockDim.x + threadIdx.x;
    if (t >= E * 32) return;
    int e = t >> 5;          // edge id (one warp per edge)
    int c = t & 31;          // float4 chunk within the row
    int s = src[e];          // broadcast within warp
    int d = dst[e];
    float4 v = reinterpret_cast<const float4*>(emb + (size_t)s * D)[c];
    red_add_v4(sum + (size_t)d * D + (size_t)c * 4, v);
}

// ---------------------------------------------------------------------------
// Fused epilogue: per-etype mean, sum over etypes, + self embed + bias, relu.
// Thread = one float4 chunk. A region first, then B.
// ---------------------------------------------------------------------------
__global__ void epilogue_kernel(const float* __restrict__ selfA,
                                const float* __restrict__ selfB,
                                const float* __restrict__ bias,
                                float*       __restrict__ out) {
    int i = blockIdx.x * blockDim.x + threadIdx.x;
    const int total = (NA + NB) * (D / 4);
    if (i >= total) return;
    int node = i >> 5;       // D/4 = 32 chunks per node
    int c    = i & 31;

    float4 b4 = reinterpret_cast<const float4*>(bias)[c];
    float4* out4 = reinterpret_cast<float4*>(out);

    if (node < NA) {
        float4 s1 = out4[i];
        float4 s2 = reinterpret_cast<const float4*>(g_sum2)[i];
        float4 sf = reinterpret_cast<const float4*>(selfA)[i];
        float inv1 = 1.0f / fmaxf((float)g_cnt1[node], 1.0f);
        float inv2 = 1.0f / fmaxf((float)g_cnt2[node], 1.0f);
        float4 r;
        r.x = fmaxf(fmaf(s1.x, inv1, fmaf(s2.x, inv2, sf.x + b4.x)), 0.f);
        r.y = fmaxf(fmaf(s1.y, inv1, fmaf(s2.y, inv2, sf.y + b4.y)), 0.f);
        r.z = fmaxf(fmaf(s1.z, inv1, fmaf(s2.z, inv2, sf.z + b4.z)), 0.f);
        r.w = fmaxf(fmaf(s1.w, inv1, fmaf(s2.w, inv2, sf.w + b4.w)), 0.f);
        out4[i] = r;
    } else {
        int nb = node - NA;
        int j  = i - NA * (D / 4);
        float4 s0 = out4[i];
        float4 sf = reinterpret_cast<const float4*>(selfB)[j];
        float inv0 = 1.0f / fmaxf((float)g_cnt0[nb], 1.0f);
        float4 r;
        r.x = fmaxf(fmaf(s0.x, inv0, sf.x + b4.x), 0.f);
        r.y = fmaxf(fmaf(s0.y, inv0, sf.y + b4.y), 0.f);
        r.z = fmaxf(fmaf(s0.z, inv0, sf.z + b4.z), 0.f);
        r.w = fmaxf(fmaf(s0.w, inv0, sf.w + b4.w), 0.f);
        out4[i] = r;
    }
}

// ---------------------------------------------------------------------------
// Launch
// ---------------------------------------------------------------------------
extern "C" void kernel_launch(void* const* d_in, const int* in_sizes, int n_in,
                              void* d_out, int out_size) {
    const float* emb0  = (const float*)d_in[0];   // srctype A, etype r0 (A->B)
    const float* emb1  = (const float*)d_in[1];   // srctype B, etype r1 (B->A)
    const float* emb2  = (const float*)d_in[2];   // srctype A, etype r2 (A->A)
    const float* selfA = (const float*)d_in[3];
    const float* selfB = (const float*)d_in[4];
    const float* bias  = (const float*)d_in[5];
    const int* src0 = (const int*)d_in[6];
    const int* dst0 = (const int*)d_in[7];
    const int* src1 = (const int*)d_in[8];
    const int* dst1 = (const int*)d_in[9];
    const int* src2 = (const int*)d_in[10];
    const int* dst2 = (const int*)d_in[11];
    const int E = in_sizes[6];

    float* out   = (float*)d_out;
    float* sumA1 = out;                       // r1 mean accumulator (dst ntype A)
    float* sumB0 = out + (size_t)NA * D;      // r0 mean accumulator (dst ntype B)

    float* sum2_ptr = nullptr;
    cudaGetSymbolAddress((void**)&sum2_ptr, g_sum2);

    const int nOut4  = (NA + NB) * (D / 4);
    const int nSum24 = NA * (D / 4);

    zero_kernel<<<(nOut4 + 255) / 256, 256>>>((float4*)out, nOut4, nSum24);
    count_kernel<<<(3 * E + 255) / 256, 256>>>(dst0, dst1, dst2, E);

    const int scatterBlocks = (E * 32 + 255) / 256;
    scatter_kernel<<<scatterBlocks, 256>>>(emb0, src0, dst0, sumB0, E);
    scatter_kernel<<<scatterBlocks, 256>>>(emb1, src1, dst1, sumA1, E);
    scatter_kernel<<<scatterBlocks, 256>>>(emb2, src2, dst2, sum2_ptr, E);

    const int epiTotal = (NA + NB) * (D / 4);
    epilogue_kernel<<<(epiTotal + 255) / 256, 256>>>(selfA, selfB, bias, out);
}

// round 4
// speedup vs baseline: 1.0120x; 1.0088x over previous
#include <cuda_runtime.h>
#include <cuda_bf16.h>
#include <cstdint>

#define NA 50000
#define NB 50000
#define D  128

// Scratch (device globals — no allocation allowed in kernel_launch).
// d_out itself is used as the accumulator for sum_r1 (A region) and sum_r0 (B region).
// g_sum2 holds the r2 (A->A) per-etype sum, since means are per-etype.
__device__ float g_sum2[(size_t)NA * D];
__device__ int   g_cnt0[NB];
__device__ int   g_cnt1[NA];
__device__ int   g_cnt2[NA];

// ---------------------------------------------------------------------------
// Zero accumulators: d_out (both regions), g_sum2, counts.
// ---------------------------------------------------------------------------
__global__ void zero_kernel(float4* __restrict__ out4, int nOut4, int nSum24) {
    int i = blockIdx.x * blockDim.x + threadIdx.x;
    const float4 z = make_float4(0.f, 0.f, 0.f, 0.f);
    if (i < nOut4)  out4[i] = z;
    if (i < nSum24) reinterpret_cast<float4*>(g_sum2)[i] = z;
    if (i < NB)     g_cnt0[i] = 0;
    if (i < NA)   { g_cnt1[i] = 0; g_cnt2[i] = 0; }
}

// ---------------------------------------------------------------------------
// Per-etype in-degree counts (int atomics).
// ---------------------------------------------------------------------------
__global__ void count_kernel(const int* __restrict__ dst0,
                             const int* __restrict__ dst1,
                             const int* __restrict__ dst2, int E) {
    int i = blockIdx.x * blockDim.x + threadIdx.x;
    if (i < E) {
        atomicAdd(&g_cnt0[dst0[i]], 1);
    } else if (i < 2 * E) {
        atomicAdd(&g_cnt1[dst1[i - E]], 1);
    } else if (i < 3 * E) {
        atomicAdd(&g_cnt2[dst2[i - 2 * E]], 1);
    }
}

// ---------------------------------------------------------------------------
// Edge scatter: warp per edge, lane c handles float4 chunk c of the D=128 row.
// Gather is coalesced (32 lanes read one 512B row); reduction uses
// red.global.add.v4.f32 (sm_90+) to quarter the atomic op count.
// ---------------------------------------------------------------------------
__device__ __forceinline__ void red_add_v4(float* p, float4 v) {
    asm volatile("red.global.add.v4.f32 [%0], {%1, %2, %3, %4};"
                 :: "l"(p), "f"(v.x), "f"(v.y), "f"(v.z), "f"(v.w)
                 : "memory");
}

__global__ void scatter_kernel(const float* __restrict__ emb,
                               const int*   __restrict__ src,
                               const int*   __restrict__ dst,
                               float*       __restrict__ sum, int E) {
    int t = blockIdx.x * blockDim.x + threadIdx.x;
    if (t >= E * 32) return;
    int e = t >> 5;          // edge id (one warp per edge)
    int c = t & 31;          // float4 chunk within the row
    int s = src[e];          // broadcast within warp
    int d = dst[e];
    float4 v = reinterpret_cast<const float4*>(emb + (size_t)s * D)[c];
    red_add_v4(sum + (size_t)d * D + (size_t)c * 4, v);
}

// ---------------------------------------------------------------------------
// Fused epilogue: per-etype mean, sum over etypes, + self embed + bias, relu.
// Thread = one float4 chunk. A region first, then B.
// ---------------------------------------------------------------------------
__global__ void epilogue_kernel(const float* __restrict__ selfA,
                                const float* __restrict__ selfB,
                                const float* __restrict__ bias,
                                float*       __restrict__ out) {
    int i = blockIdx.x * blockDim.x + threadIdx.x;
    const int total = (NA + NB) * (D / 4);
    if (i >= total) return;
    int node = i >> 5;       // D/4 = 32 chunks per node
    int c    = i & 31;

    float4 b4 = reinterpret_cast<const float4*>(bias)[c];
    float4* out4 = reinterpret_cast<float4*>(out);

    if (node < NA) {
        float4 s1 = out4[i];
        float4 s2 = reinterpret_cast<const float4*>(g_sum2)[i];
        float4 sf = reinterpret_cast<const float4*>(selfA)[i];
        float inv1 = 1.0f / fmaxf((float)g_cnt1[node], 1.0f);
        float inv2 = 1.0f / fmaxf((float)g_cnt2[node], 1.0f);
        float4 r;
        r.x = fmaxf(fmaf(s1.x, inv1, fmaf(s2.x, inv2, sf.x + b4.x)), 0.f);
        r.y = fmaxf(fmaf(s1.y, inv1, fmaf(s2.y, inv2, sf.y + b4.y)), 0.f);
        r.z = fmaxf(fmaf(s1.z, inv1, fmaf(s2.z, inv2, sf.z + b4.z)), 0.f);
        r.w = fmaxf(fmaf(s1.w, inv1, fmaf(s2.w, inv2, sf.w + b4.w)), 0.f);
        out4[i] = r;
    } else {
        int nb = node - NA;
        int j  = i - NA * (D / 4);
        float4 s0 = out4[i];
        float4 sf = reinterpret_cast<const float4*>(selfB)[j];
        float inv0 = 1.0f / fmaxf((float)g_cnt0[nb], 1.0f);
        float4 r;
        r.x = fmaxf(fmaf(s0.x, inv0, sf.x + b4.x), 0.f);
        r.y = fmaxf(fmaf(s0.y, inv0, sf.y + b4.y), 0.f);
        r.z = fmaxf(fmaf(s0.z, inv0, sf.z + b4.z), 0.f);
        r.w = fmaxf(fmaf(s0.w, inv0, sf.w + b4.w), 0.f);
        out4[i] = r;
    }
}

// ---------------------------------------------------------------------------
// Launch
// ---------------------------------------------------------------------------
extern "C" void kernel_launch(void* const* d_in, const int* in_sizes, int n_in,
                              void* d_out, int out_size) {
    const float* emb0  = (const float*)d_in[0];   // srctype A, etype r0 (A->B)
    const float* emb1  = (const float*)d_in[1];   // srctype B, etype r1 (B->A)
    const float* emb2  = (const float*)d_in[2];   // srctype A, etype r2 (A->A)
    const float* selfA = (const float*)d_in[3];
    const float* selfB = (const float*)d_in[4];
    const float* bias  = (const float*)d_in[5];
    const int* src0 = (const int*)d_in[6];
    const int* dst0 = (const int*)d_in[7];
    const int* src1 = (const int*)d_in[8];
    const int* dst1 = (const int*)d_in[9];
    const int* src2 = (const int*)d_in[10];
    const int* dst2 = (const int*)d_in[11];
    const int E = in_sizes[6];

    float* out   = (float*)d_out;
    float* sumA1 = out;                       // r1 mean accumulator (dst ntype A)
    float* sumB0 = out + (size_t)NA * D;      // r0 mean accumulator (dst ntype B)

    float* sum2_ptr = nullptr;
    cudaGetSymbolAddress((void**)&sum2_ptr, g_sum2);

    const int nOut4  = (NA + NB) * (D / 4);
    const int nSum24 = NA * (D / 4);

    zero_kernel<<<(nOut4 + 255) / 256, 256>>>((float4*)out, nOut4, nSum24);
    count_kernel<<<(3 * E + 255) / 256, 256>>>(dst0, dst1, dst2, E);

    const int scatterBlocks = (E * 32 + 255) / 256;
    scatter_kernel<<<scatterBlocks, 256>>>(emb0, src0, dst0, sumB0, E);
    scatter_kernel<<<scatterBlocks, 256>>>(emb1, src1, dst1, sumA1, E);
    scatter_kernel<<<scatterBlocks, 256>>>(emb2, src2, dst2, sum2_ptr, E);

    const int epiTotal = (NA + NB) * (D / 4);
    epilogue_kernel<<<(epiTotal + 255) / 256, 256>>>(selfA, selfB, bias, out);
}